// round 2
// baseline (speedup 1.0000x reference)
#include <cuda_runtime.h>
#include <cuda_bf16.h>

#define NNODES 100000
#define NEDGES 3200000
#define IN_DIM 23
#define INP 24          // padded input dim (24*4B = 96B rows, 16B-aligned)
#define HID 128

// ---------------- scratch (static device globals; no allocation) ----------------
__device__ __align__(16) float g_dis[NNODES];          // deg -> rsqrt(deg) in place
__device__ __align__(16) float g_xpad[NNODES * INP];   // x padded to 24
__device__ __align__(16) float g_aggx[NNODES * INP];   // aggregated input features
__device__ __align__(16) float g_bufA[NNODES * HID];
__device__ __align__(16) float g_bufB[NNODES * HID];

// ---------------- helpers ----------------
__device__ __forceinline__ void red_add_v4(float* addr, float4 v) {
    asm volatile("red.global.add.v4.f32 [%0], {%1,%2,%3,%4};"
                 :: "l"(__cvta_generic_to_global(addr)),
                    "f"(v.x), "f"(v.y), "f"(v.z), "f"(v.w)
                 : "memory");
}

// ---------------- degree / normalization ----------------
__global__ void k_deg_init(float* deg, int n) {
    int i = blockIdx.x * blockDim.x + threadIdx.x;
    if (i < n) deg[i] = 1.0f;   // self loop
}

__global__ void k_deg_count(const int* __restrict__ ei, float* deg, int E) {
    int e = blockIdx.x * blockDim.x + threadIdx.x;
    if (e < E) {
        int d = ei[E + e];
        atomicAdd(&deg[d], 1.0f);
    }
}

__global__ void k_dis(float* deg, int n) {
    int i = blockIdx.x * blockDim.x + threadIdx.x;
    if (i < n) deg[i] = rsqrtf(deg[i]);
}

// pad x to 24 wide, and initialize aggx with the self-loop term dis[i]^2 * x[i]
__global__ void k_prep_x(const float* __restrict__ x, const float* __restrict__ dis,
                         float* __restrict__ xp, float* __restrict__ aggx, int n) {
    int idx = blockIdx.x * blockDim.x + threadIdx.x;
    if (idx < n * INP) {
        int node = idx / INP;
        int f = idx - node * INP;
        float v = (f < IN_DIM) ? x[node * IN_DIM + f] : 0.0f;
        xp[idx] = v;
        float s = dis[node];
        aggx[idx] = s * s * v;
    }
}

// scatter for padded-24 features: thread = (edge, float4-chunk), 6 chunks/edge
__global__ void k_scatter24(const int* __restrict__ ei, const float* __restrict__ dis,
                            const float4* __restrict__ xp4, float* __restrict__ agg, int E) {
    int t = blockIdx.x * blockDim.x + threadIdx.x;
    int e = t / 6;
    if (e < E) {
        int j = t - e * 6;
        int s = ei[e];
        int d = ei[E + e];
        float n = dis[s] * dis[d];
        float4 v = xp4[s * 6 + j];
        v.x *= n; v.y *= n; v.z *= n; v.w *= n;
        red_add_v4(agg + (d * INP + j * 4), v);
    }
}

// self-loop init for 128-dim features: agg[i] = dis[i]^2 * h[i]
__global__ void k_selfloop128(const float* __restrict__ dis, const float4* __restrict__ h4,
                              float4* __restrict__ agg4, int n) {
    int idx = blockIdx.x * blockDim.x + threadIdx.x;
    if (idx < n * 32) {
        int node = idx >> 5;
        float s = dis[node]; s *= s;
        float4 v = h4[idx];
        v.x *= s; v.y *= s; v.z *= s; v.w *= s;
        agg4[idx] = v;
    }
}

// scatter for 128-dim features: thread = (edge, float4-chunk), 32 chunks/edge
__global__ void k_scatter128(const int* __restrict__ ei, const float* __restrict__ dis,
                             const float4* __restrict__ h4, float* __restrict__ agg, int E) {
    int t = blockIdx.x * blockDim.x + threadIdx.x;
    int e = t >> 5;
    if (e < E) {
        int j = t & 31;
        int s = ei[e];
        int d = ei[E + e];
        float n = dis[s] * dis[d];
        float4 v = h4[s * 32 + j];
        v.x *= n; v.y *= n; v.z *= n; v.w *= n;
        red_add_v4(agg + (d * HID + j * 4), v);
    }
}

// ---------------- GEMM: out[M,128] = act(A[M,K] @ W[K,128] + b) ----------------
// Block tile: 64 rows x 128 cols, 256 threads, 4x8 per-thread micro-tile.
// K chunked by 32 through shared memory (A staged transposed).
__global__ void __launch_bounds__(256)
k_gemm(const float* __restrict__ A, int lda, int K,
       const float* __restrict__ W, const float* __restrict__ bias,
       float* __restrict__ out, int M, int do_relu) {
    __shared__ float As[32][68];    // [k][row], row-padded
    __shared__ float Ws[32][HID];   // [k][col]

    int tid = threadIdx.x;
    int row0 = blockIdx.x * 64;
    int cg = tid & 15;       // column group: cols cg*4..+3 and cg*4+64..+3
    int rg = tid >> 4;       // row group: rows rg*4..+3

    float acc[4][8];
    #pragma unroll
    for (int i = 0; i < 4; i++)
        #pragma unroll
        for (int j = 0; j < 8; j++) acc[i][j] = 0.0f;

    int nChunks = (K + 31) / 32;
    for (int kc = 0; kc < nChunks; kc++) {
        int k0 = kc * 32;
        // --- load A chunk (64 rows x 32 k), transposed into As[k][row] ---
        #pragma unroll
        for (int q = 0; q < 2; q++) {
            int s = tid * 2 + q;          // 0..511 float4 slots
            int r = s >> 3;               // 0..63
            int kk4 = (s & 7) * 4;        // 0,4,...,28
            int grow = row0 + r;
            int k = k0 + kk4;
            float4 v = make_float4(0.f, 0.f, 0.f, 0.f);
            if (grow < M) {
                if (k + 4 <= lda) {
                    v = *(const float4*)&A[grow * lda + k];
                } else {
                    float* pv = &v.x;
                    #pragma unroll
                    for (int u = 0; u < 4; u++)
                        if (k + u < lda) pv[u] = A[grow * lda + k + u];
                }
            }
            As[kk4 + 0][r] = v.x;
            As[kk4 + 1][r] = v.y;
            As[kk4 + 2][r] = v.z;
            As[kk4 + 3][r] = v.w;
        }
        // --- load W chunk (32 k x 128 cols) ---
        #pragma unroll
        for (int q = 0; q < 4; q++) {
            int s = tid + q * 256;        // 0..1023 float4 slots
            int kk = s >> 5;
            int c = (s & 31) * 4;
            int k = k0 + kk;
            float4 v = make_float4(0.f, 0.f, 0.f, 0.f);
            if (k < K) v = *(const float4*)&W[k * HID + c];
            *(float4*)&Ws[kk][c] = v;
        }
        __syncthreads();

        #pragma unroll
        for (int kk = 0; kk < 32; kk++) {
            float4 a  = *(float4*)&As[kk][rg * 4];
            float4 w0 = *(float4*)&Ws[kk][cg * 4];
            float4 w1 = *(float4*)&Ws[kk][cg * 4 + 64];
            float av[4] = {a.x, a.y, a.z, a.w};
            float wv[8] = {w0.x, w0.y, w0.z, w0.w, w1.x, w1.y, w1.z, w1.w};
            #pragma unroll
            for (int i = 0; i < 4; i++)
                #pragma unroll
                for (int j = 0; j < 8; j++)
                    acc[i][j] += av[i] * wv[j];
        }
        __syncthreads();
    }

    // --- epilogue: bias, optional relu, store ---
    float bv[8];
    #pragma unroll
    for (int j = 0; j < 4; j++) {
        bv[j]     = bias[cg * 4 + j];
        bv[j + 4] = bias[cg * 4 + 64 + j];
    }
    #pragma unroll
    for (int i = 0; i < 4; i++) {
        int grow = row0 + rg * 4 + i;
        if (grow < M) {
            float o[8];
            #pragma unroll
            for (int j = 0; j < 8; j++) {
                float v = acc[i][j] + bv[j];
                if (do_relu) v = fmaxf(v, 0.0f);
                o[j] = v;
            }
            *(float4*)&out[grow * HID + cg * 4]      = make_float4(o[0], o[1], o[2], o[3]);
            *(float4*)&out[grow * HID + cg * 4 + 64] = make_float4(o[4], o[5], o[6], o[7]);
        }
    }
}

// ---------------- launch ----------------
extern "C" void kernel_launch(void* const* d_in, const int* in_sizes, int n_in,
                              void* d_out, int out_size) {
    const float* x  = (const float*)d_in[0];
    const int*   ei = (const int*)d_in[1];   // int32! (JAX x64 disabled)
    const float* W1 = (const float*)d_in[2]; const float* b1 = (const float*)d_in[3];
    const float* W2 = (const float*)d_in[4]; const float* b2 = (const float*)d_in[5];
    const float* W3 = (const float*)d_in[6]; const float* b3 = (const float*)d_in[7];
    const float* W4 = (const float*)d_in[8]; const float* b4 = (const float*)d_in[9];
    float* out = (float*)d_out;

    int E = in_sizes[1] / 2;
    int N = out_size / HID;

    void* p;
    cudaGetSymbolAddress(&p, g_dis);  float* dis  = (float*)p;
    cudaGetSymbolAddress(&p, g_xpad); float* xpad = (float*)p;
    cudaGetSymbolAddress(&p, g_aggx); float* aggx = (float*)p;
    cudaGetSymbolAddress(&p, g_bufA); float* bufA = (float*)p;
    cudaGetSymbolAddress(&p, g_bufB); float* bufB = (float*)p;

    const int T = 256;
    int blkN    = (N + T - 1) / T;
    int blkE    = (E + T - 1) / T;
    int blkPrep = (N * INP + T - 1) / T;
    int blkSL   = (N * 32 + T - 1) / T;
    int blkS24  = (E * 6 + T - 1) / T;
    int blkS128 = (E * 32 + T - 1) / T;
    int blkG    = (N + 63) / 64;

    // normalization
    k_deg_init<<<blkN, T>>>(dis, N);
    k_deg_count<<<blkE, T>>>(ei, dis, E);
    k_dis<<<blkN, T>>>(dis, N);

    // layer 1: aggregate x (24-wide padded), then GEMM 23->128 + relu
    k_prep_x<<<blkPrep, T>>>(x, dis, xpad, aggx, N);
    k_scatter24<<<blkS24, T>>>(ei, dis, (const float4*)xpad, aggx, E);
    k_gemm<<<blkG, T>>>(aggx, INP, IN_DIM, W1, b1, bufA, N, 1);

    // layer 2: agg(bufA)->bufB, GEMM in-place bufB
    k_selfloop128<<<blkSL, T>>>(dis, (const float4*)bufA, (float4*)bufB, N);
    k_scatter128<<<blkS128, T>>>(ei, dis, (const float4*)bufA, bufB, E);
    k_gemm<<<blkG, T>>>(bufB, HID, HID, W2, b2, bufB, N, 1);

    // layer 3: agg(bufB)->bufA, GEMM in-place bufA
    k_selfloop128<<<blkSL, T>>>(dis, (const float4*)bufB, (float4*)bufA, N);
    k_scatter128<<<blkS128, T>>>(ei, dis, (const float4*)bufB, bufA, E);
    k_gemm<<<blkG, T>>>(bufA, HID, HID, W3, b3, bufA, N, 1);

    // layer 4: agg(bufA)->bufB, GEMM bufB -> out (no relu)
    k_selfloop128<<<blkSL, T>>>(dis, (const float4*)bufA, (float4*)bufB, N);
    k_scatter128<<<blkS128, T>>>(ei, dis, (const float4*)bufA, bufB, E);
    k_gemm<<<blkG, T>>>(bufB, HID, HID, W4, b4, out, N, 0);
}

// round 3
// speedup vs baseline: 2.2238x; 2.2238x over previous
#include <cuda_runtime.h>
#include <cuda_bf16.h>

#define NNODES 100000
#define NEDGES 3200000
#define IN_DIM 23
#define INP 24          // padded input dim (24*4B = 96B rows, 16B-aligned)
#define HID 128
#define SCAN_B 1024

// ---------------- scratch (static device globals; no allocation) ----------------
__device__ __align__(16) float g_dis[NNODES];
__device__ __align__(16) float g_xpad[NNODES * INP];
__device__ __align__(16) float g_aggx[NNODES * INP];
__device__ __align__(16) float g_bufA[NNODES * HID];
__device__ __align__(16) float g_bufB[NNODES * HID];
__device__ int   g_deg[NNODES];
__device__ int   g_rowptr[NNODES];
__device__ int   g_cursor[NNODES];
__device__ int   g_bsum[256];
__device__ __align__(16) int   g_csr_src[NEDGES];
__device__ __align__(16) float g_csr_w[NEDGES];

// ---------------- degree / normalization ----------------
__global__ void k_deg_zero(int* deg, int n) {
    int i = blockIdx.x * blockDim.x + threadIdx.x;
    if (i < n) deg[i] = 0;
}

__global__ void k_deg_count(const int* __restrict__ ei, int* deg, int E) {
    int e = blockIdx.x * blockDim.x + threadIdx.x;
    if (e < E) atomicAdd(&deg[ei[E + e]], 1);
}

__global__ void k_dis(const int* __restrict__ deg, float* dis, int n) {
    int i = blockIdx.x * blockDim.x + threadIdx.x;
    if (i < n) dis[i] = rsqrtf((float)(deg[i] + 1));   // +1 self loop
}

// ---------------- CSR build: exclusive scan of degrees ----------------
__global__ void k_scan_block(const int* __restrict__ deg, int* excl, int* bsum, int n) {
    __shared__ int sh[SCAN_B];
    int t = threadIdx.x;
    int i = blockIdx.x * SCAN_B + t;
    int v = (i < n) ? deg[i] : 0;
    sh[t] = v;
    __syncthreads();
    #pragma unroll
    for (int off = 1; off < SCAN_B; off <<= 1) {
        int add = (t >= off) ? sh[t - off] : 0;
        __syncthreads();
        sh[t] += add;
        __syncthreads();
    }
    if (i < n) excl[i] = sh[t] - v;                 // exclusive
    if (t == SCAN_B - 1) bsum[blockIdx.x] = sh[t];  // block total
}

__global__ void k_scan_bsum(int* bsum, int nblk) {
    if (blockIdx.x == 0 && threadIdx.x == 0) {
        int acc = 0;
        for (int b = 0; b < nblk; b++) { int v = bsum[b]; bsum[b] = acc; acc += v; }
    }
}

__global__ void k_scan_add(int* excl, int* cursor, const int* __restrict__ bsum, int n) {
    int i = blockIdx.x * blockDim.x + threadIdx.x;
    if (i < n) {
        int v = excl[i] + bsum[i / SCAN_B];
        excl[i] = v;
        cursor[i] = v;
    }
}

// fill CSR: per-edge slot via atomic cursor; precompute edge norm weight
__global__ void k_fill(const int* __restrict__ ei, const float* __restrict__ dis,
                       int* cursor, int* csr_src, float* csr_w, int E) {
    int e = blockIdx.x * blockDim.x + threadIdx.x;
    if (e < E) {
        int s = ei[e];
        int d = ei[E + e];
        int pos = atomicAdd(&cursor[d], 1);
        csr_src[pos] = s;
        csr_w[pos]   = dis[s] * dis[d];
    }
}

// ---------------- x padding ----------------
__global__ void k_prep_x(const float* __restrict__ x, float* __restrict__ xp, int n) {
    int idx = blockIdx.x * blockDim.x + threadIdx.x;
    if (idx < n * INP) {
        int node = idx / INP;
        int f = idx - node * INP;
        xp[idx] = (f < IN_DIM) ? x[node * IN_DIM + f] : 0.0f;
    }
}

// ---------------- pull gather: warp per node ----------------
// 128-dim: lane l owns float4 chunk l (cols 4l..4l+3)
__global__ void __launch_bounds__(256)
k_gather128(const int* __restrict__ rowptr, const int* __restrict__ deg,
            const int* __restrict__ csr_src, const float* __restrict__ csr_w,
            const float* __restrict__ dis,
            const float4* __restrict__ h4, float4* __restrict__ out4, int n) {
    int warp = (blockIdx.x * blockDim.x + threadIdx.x) >> 5;
    int lane = threadIdx.x & 31;
    if (warp >= n) return;

    float s = dis[warp];
    float4 a = h4[warp * 32 + lane];
    float s2 = s * s;
    float4 acc = make_float4(a.x * s2, a.y * s2, a.z * s2, a.w * s2);

    int e   = rowptr[warp];
    int end = e + deg[warp];

    for (; e + 4 <= end; e += 4) {
        int   s0 = __ldg(&csr_src[e]),   s1 = __ldg(&csr_src[e+1]);
        int   s2i= __ldg(&csr_src[e+2]), s3 = __ldg(&csr_src[e+3]);
        float w0 = __ldg(&csr_w[e]),     w1 = __ldg(&csr_w[e+1]);
        float w2 = __ldg(&csr_w[e+2]),   w3 = __ldg(&csr_w[e+3]);
        float4 v0 = h4[s0  * 32 + lane];
        float4 v1 = h4[s1  * 32 + lane];
        float4 v2 = h4[s2i * 32 + lane];
        float4 v3 = h4[s3  * 32 + lane];
        acc.x += w0*v0.x + w1*v1.x + w2*v2.x + w3*v3.x;
        acc.y += w0*v0.y + w1*v1.y + w2*v2.y + w3*v3.y;
        acc.z += w0*v0.z + w1*v1.z + w2*v2.z + w3*v3.z;
        acc.w += w0*v0.w + w1*v1.w + w2*v2.w + w3*v3.w;
    }
    for (; e < end; e++) {
        int   si = __ldg(&csr_src[e]);
        float w  = __ldg(&csr_w[e]);
        float4 v = h4[si * 32 + lane];
        acc.x += w*v.x; acc.y += w*v.y; acc.z += w*v.z; acc.w += w*v.w;
    }
    out4[warp * 32 + lane] = acc;
}

// 24-dim (padded): lanes 0..5 own float4 chunks
__global__ void __launch_bounds__(256)
k_gather24(const int* __restrict__ rowptr, const int* __restrict__ deg,
           const int* __restrict__ csr_src, const float* __restrict__ csr_w,
           const float* __restrict__ dis,
           const float4* __restrict__ x4, float4* __restrict__ out4, int n) {
    int warp = (blockIdx.x * blockDim.x + threadIdx.x) >> 5;
    int lane = threadIdx.x & 31;
    if (warp >= n) return;
    bool act = lane < 6;

    float s = dis[warp];
    float s2 = s * s;
    float4 acc = make_float4(0.f, 0.f, 0.f, 0.f);
    if (act) {
        float4 a = x4[warp * 6 + lane];
        acc = make_float4(a.x * s2, a.y * s2, a.z * s2, a.w * s2);
    }

    int e   = rowptr[warp];
    int end = e + deg[warp];
    for (; e + 2 <= end; e += 2) {
        int   s0 = __ldg(&csr_src[e]),  s1 = __ldg(&csr_src[e+1]);
        float w0 = __ldg(&csr_w[e]),    w1 = __ldg(&csr_w[e+1]);
        if (act) {
            float4 v0 = x4[s0 * 6 + lane];
            float4 v1 = x4[s1 * 6 + lane];
            acc.x += w0*v0.x + w1*v1.x;
            acc.y += w0*v0.y + w1*v1.y;
            acc.z += w0*v0.z + w1*v1.z;
            acc.w += w0*v0.w + w1*v1.w;
        }
    }
    for (; e < end; e++) {
        int   si = __ldg(&csr_src[e]);
        float w  = __ldg(&csr_w[e]);
        if (act) {
            float4 v = x4[si * 6 + lane];
            acc.x += w*v.x; acc.y += w*v.y; acc.z += w*v.z; acc.w += w*v.w;
        }
    }
    if (act) out4[warp * 6 + lane] = acc;
}

// ---------------- GEMM: out[M,128] = act(A[M,K] @ W[K,128] + b) ----------------
__global__ void __launch_bounds__(256)
k_gemm(const float* __restrict__ A, int lda, int K,
       const float* __restrict__ W, const float* __restrict__ bias,
       float* __restrict__ out, int M, int do_relu) {
    __shared__ float As[32][68];
    __shared__ float Ws[32][HID];

    int tid = threadIdx.x;
    int row0 = blockIdx.x * 64;
    int cg = tid & 15;
    int rg = tid >> 4;

    float acc[4][8];
    #pragma unroll
    for (int i = 0; i < 4; i++)
        #pragma unroll
        for (int j = 0; j < 8; j++) acc[i][j] = 0.0f;

    int nChunks = (K + 31) / 32;
    for (int kc = 0; kc < nChunks; kc++) {
        int k0 = kc * 32;
        #pragma unroll
        for (int q = 0; q < 2; q++) {
            int s = tid * 2 + q;
            int r = s >> 3;
            int kk4 = (s & 7) * 4;
            int grow = row0 + r;
            int k = k0 + kk4;
            float4 v = make_float4(0.f, 0.f, 0.f, 0.f);
            if (grow < M) {
                if (k + 4 <= lda) {
                    v = *(const float4*)&A[grow * lda + k];
                } else {
                    float* pv = &v.x;
                    #pragma unroll
                    for (int u = 0; u < 4; u++)
                        if (k + u < lda) pv[u] = A[grow * lda + k + u];
                }
            }
            As[kk4 + 0][r] = v.x;
            As[kk4 + 1][r] = v.y;
            As[kk4 + 2][r] = v.z;
            As[kk4 + 3][r] = v.w;
        }
        #pragma unroll
        for (int q = 0; q < 4; q++) {
            int s = tid + q * 256;
            int kk = s >> 5;
            int c = (s & 31) * 4;
            int k = k0 + kk;
            float4 v = make_float4(0.f, 0.f, 0.f, 0.f);
            if (k < K) v = *(const float4*)&W[k * HID + c];
            *(float4*)&Ws[kk][c] = v;
        }
        __syncthreads();

        #pragma unroll
        for (int kk = 0; kk < 32; kk++) {
            float4 a  = *(float4*)&As[kk][rg * 4];
            float4 w0 = *(float4*)&Ws[kk][cg * 4];
            float4 w1 = *(float4*)&Ws[kk][cg * 4 + 64];
            float av[4] = {a.x, a.y, a.z, a.w};
            float wv[8] = {w0.x, w0.y, w0.z, w0.w, w1.x, w1.y, w1.z, w1.w};
            #pragma unroll
            for (int i = 0; i < 4; i++)
                #pragma unroll
                for (int j = 0; j < 8; j++)
                    acc[i][j] += av[i] * wv[j];
        }
        __syncthreads();
    }

    float bv[8];
    #pragma unroll
    for (int j = 0; j < 4; j++) {
        bv[j]     = bias[cg * 4 + j];
        bv[j + 4] = bias[cg * 4 + 64 + j];
    }
    #pragma unroll
    for (int i = 0; i < 4; i++) {
        int grow = row0 + rg * 4 + i;
        if (grow < M) {
            float o[8];
            #pragma unroll
            for (int j = 0; j < 8; j++) {
                float v = acc[i][j] + bv[j];
                if (do_relu) v = fmaxf(v, 0.0f);
                o[j] = v;
            }
            *(float4*)&out[grow * HID + cg * 4]      = make_float4(o[0], o[1], o[2], o[3]);
            *(float4*)&out[grow * HID + cg * 4 + 64] = make_float4(o[4], o[5], o[6], o[7]);
        }
    }
}

// ---------------- launch ----------------
extern "C" void kernel_launch(void* const* d_in, const int* in_sizes, int n_in,
                              void* d_out, int out_size) {
    const float* x  = (const float*)d_in[0];
    const int*   ei = (const int*)d_in[1];   // int32 (JAX x64 disabled)
    const float* W1 = (const float*)d_in[2]; const float* b1 = (const float*)d_in[3];
    const float* W2 = (const float*)d_in[4]; const float* b2 = (const float*)d_in[5];
    const float* W3 = (const float*)d_in[6]; const float* b3 = (const float*)d_in[7];
    const float* W4 = (const float*)d_in[8]; const float* b4 = (const float*)d_in[9];
    float* out = (float*)d_out;

    int E = in_sizes[1] / 2;
    int N = out_size / HID;

    void* p;
    cudaGetSymbolAddress(&p, g_dis);     float* dis  = (float*)p;
    cudaGetSymbolAddress(&p, g_xpad);    float* xpad = (float*)p;
    cudaGetSymbolAddress(&p, g_aggx);    float* aggx = (float*)p;
    cudaGetSymbolAddress(&p, g_bufA);    float* bufA = (float*)p;
    cudaGetSymbolAddress(&p, g_bufB);    float* bufB = (float*)p;
    cudaGetSymbolAddress(&p, g_deg);     int* deg    = (int*)p;
    cudaGetSymbolAddress(&p, g_rowptr);  int* rowptr = (int*)p;
    cudaGetSymbolAddress(&p, g_cursor);  int* cursor = (int*)p;
    cudaGetSymbolAddress(&p, g_bsum);    int* bsum   = (int*)p;
    cudaGetSymbolAddress(&p, g_csr_src); int* csr_src= (int*)p;
    cudaGetSymbolAddress(&p, g_csr_w);   float* csr_w= (float*)p;

    const int T = 256;
    int blkN    = (N + T - 1) / T;
    int blkE    = (E + T - 1) / T;
    int blkPrep = (N * INP + T - 1) / T;
    int nScanB  = (N + SCAN_B - 1) / SCAN_B;
    int blkWarp = (N * 32 + T - 1) / T;     // warp-per-node kernels
    int blkG    = (N + 63) / 64;

    // norm + CSR build
    k_deg_zero<<<blkN, T>>>(deg, N);
    k_deg_count<<<blkE, T>>>(ei, deg, E);
    k_dis<<<blkN, T>>>(deg, dis, N);
    k_scan_block<<<nScanB, SCAN_B>>>(deg, rowptr, bsum, N);
    k_scan_bsum<<<1, 32>>>(bsum, nScanB);
    k_scan_add<<<blkN, T>>>(rowptr, cursor, bsum, N);
    k_fill<<<blkE, T>>>(ei, dis, cursor, csr_src, csr_w, E);

    // layer 1: pad x, gather 24-wide, GEMM 23->128 + relu
    k_prep_x<<<blkPrep, T>>>(x, xpad, N);
    k_gather24<<<blkWarp, T>>>(rowptr, deg, csr_src, csr_w, dis,
                               (const float4*)xpad, (float4*)aggx, N);
    k_gemm<<<blkG, T>>>(aggx, INP, IN_DIM, W1, b1, bufA, N, 1);

    // layer 2
    k_gather128<<<blkWarp, T>>>(rowptr, deg, csr_src, csr_w, dis,
                                (const float4*)bufA, (float4*)bufB, N);
    k_gemm<<<blkG, T>>>(bufB, HID, HID, W2, b2, bufB, N, 1);

    // layer 3
    k_gather128<<<blkWarp, T>>>(rowptr, deg, csr_src, csr_w, dis,
                                (const float4*)bufB, (float4*)bufA, N);
    k_gemm<<<blkG, T>>>(bufA, HID, HID, W3, b3, bufA, N, 1);

    // layer 4 (no relu) -> out
    k_gather128<<<blkWarp, T>>>(rowptr, deg, csr_src, csr_w, dis,
                                (const float4*)bufA, (float4*)bufB, N);
    k_gemm<<<blkG, T>>>(bufB, HID, HID, W4, b4, out, N, 0);
}

// round 4
// speedup vs baseline: 2.5901x; 1.1647x over previous
#include <cuda_runtime.h>
#include <cuda_bf16.h>

#define NNODES 100000
#define NEDGES 3200000
#define IN_DIM 23
#define INP 24          // padded input dim (24*4B = 96B rows, 16B-aligned)
#define HID 128
#define SCAN_B 1024

// ---------------- scratch (static device globals; no allocation) ----------------
__device__ __align__(16) float g_dis[NNODES];
__device__ __align__(16) float g_xpad[NNODES * INP];
__device__ __align__(16) float g_aggx[NNODES * INP];
__device__ __align__(16) float g_bufA[NNODES * HID];
__device__ __align__(16) float g_bufB[NNODES * HID];
__device__ int   g_deg[NNODES];
__device__ int   g_rowptr[NNODES];
__device__ int   g_cursor[NNODES];
__device__ int   g_bsum[256];
__device__ __align__(16) int   g_csr_src[NEDGES];
__device__ __align__(16) float g_csr_w[NEDGES];

// ---------------- degree / normalization ----------------
__global__ void k_deg_zero(int* deg, int n) {
    int i = blockIdx.x * blockDim.x + threadIdx.x;
    if (i < n) deg[i] = 0;
}

__global__ void k_deg_count(const int* __restrict__ ei, int* deg, int E) {
    int e = blockIdx.x * blockDim.x + threadIdx.x;
    if (e < E) atomicAdd(&deg[ei[E + e]], 1);
}

__global__ void k_dis(const int* __restrict__ deg, float* dis, int n) {
    int i = blockIdx.x * blockDim.x + threadIdx.x;
    if (i < n) dis[i] = rsqrtf((float)(deg[i] + 1));   // +1 self loop
}

// ---------------- CSR build: exclusive scan of degrees ----------------
__global__ void k_scan_block(const int* __restrict__ deg, int* excl, int* bsum, int n) {
    __shared__ int sh[SCAN_B];
    int t = threadIdx.x;
    int i = blockIdx.x * SCAN_B + t;
    int v = (i < n) ? deg[i] : 0;
    sh[t] = v;
    __syncthreads();
    #pragma unroll
    for (int off = 1; off < SCAN_B; off <<= 1) {
        int add = (t >= off) ? sh[t - off] : 0;
        __syncthreads();
        sh[t] += add;
        __syncthreads();
    }
    if (i < n) excl[i] = sh[t] - v;
    if (t == SCAN_B - 1) bsum[blockIdx.x] = sh[t];
}

__global__ void k_scan_bsum(int* bsum, int nblk) {
    if (blockIdx.x == 0 && threadIdx.x == 0) {
        int acc = 0;
        for (int b = 0; b < nblk; b++) { int v = bsum[b]; bsum[b] = acc; acc += v; }
    }
}

__global__ void k_scan_add(int* excl, int* cursor, const int* __restrict__ bsum, int n) {
    int i = blockIdx.x * blockDim.x + threadIdx.x;
    if (i < n) {
        int v = excl[i] + bsum[i / SCAN_B];
        excl[i] = v;
        cursor[i] = v;
    }
}

__global__ void k_fill(const int* __restrict__ ei, const float* __restrict__ dis,
                       int* cursor, int* csr_src, float* csr_w, int E) {
    int e = blockIdx.x * blockDim.x + threadIdx.x;
    if (e < E) {
        int s = ei[e];
        int d = ei[E + e];
        int pos = atomicAdd(&cursor[d], 1);
        csr_src[pos] = s;
        csr_w[pos]   = dis[s] * dis[d];
    }
}

// ---------------- x padding ----------------
__global__ void k_prep_x(const float* __restrict__ x, float* __restrict__ xp, int n) {
    int idx = blockIdx.x * blockDim.x + threadIdx.x;
    if (idx < n * INP) {
        int node = idx / INP;
        int f = idx - node * INP;
        xp[idx] = (f < IN_DIM) ? x[node * IN_DIM + f] : 0.0f;
    }
}

// ---------------- pull gather: warp per node ----------------
__global__ void __launch_bounds__(256)
k_gather128(const int* __restrict__ rowptr, const int* __restrict__ deg,
            const int* __restrict__ csr_src, const float* __restrict__ csr_w,
            const float* __restrict__ dis,
            const float4* __restrict__ h4, float4* __restrict__ out4, int n) {
    int warp = (blockIdx.x * blockDim.x + threadIdx.x) >> 5;
    int lane = threadIdx.x & 31;
    if (warp >= n) return;

    float s = dis[warp];
    float4 a = h4[warp * 32 + lane];
    float s2 = s * s;
    float4 acc = make_float4(a.x * s2, a.y * s2, a.z * s2, a.w * s2);

    int e   = rowptr[warp];
    int end = e + deg[warp];

    for (; e + 4 <= end; e += 4) {
        int   s0 = __ldg(&csr_src[e]),   s1 = __ldg(&csr_src[e+1]);
        int   s2i= __ldg(&csr_src[e+2]), s3 = __ldg(&csr_src[e+3]);
        float w0 = __ldg(&csr_w[e]),     w1 = __ldg(&csr_w[e+1]);
        float w2 = __ldg(&csr_w[e+2]),   w3 = __ldg(&csr_w[e+3]);
        float4 v0 = h4[s0  * 32 + lane];
        float4 v1 = h4[s1  * 32 + lane];
        float4 v2 = h4[s2i * 32 + lane];
        float4 v3 = h4[s3  * 32 + lane];
        acc.x += w0*v0.x + w1*v1.x + w2*v2.x + w3*v3.x;
        acc.y += w0*v0.y + w1*v1.y + w2*v2.y + w3*v3.y;
        acc.z += w0*v0.z + w1*v1.z + w2*v2.z + w3*v3.z;
        acc.w += w0*v0.w + w1*v1.w + w2*v2.w + w3*v3.w;
    }
    for (; e < end; e++) {
        int   si = __ldg(&csr_src[e]);
        float w  = __ldg(&csr_w[e]);
        float4 v = h4[si * 32 + lane];
        acc.x += w*v.x; acc.y += w*v.y; acc.z += w*v.z; acc.w += w*v.w;
    }
    out4[warp * 32 + lane] = acc;
}

__global__ void __launch_bounds__(256)
k_gather24(const int* __restrict__ rowptr, const int* __restrict__ deg,
           const int* __restrict__ csr_src, const float* __restrict__ csr_w,
           const float* __restrict__ dis,
           const float4* __restrict__ x4, float4* __restrict__ out4, int n) {
    int warp = (blockIdx.x * blockDim.x + threadIdx.x) >> 5;
    int lane = threadIdx.x & 31;
    if (warp >= n) return;
    bool act = lane < 6;

    float s = dis[warp];
    float s2 = s * s;
    float4 acc = make_float4(0.f, 0.f, 0.f, 0.f);
    if (act) {
        float4 a = x4[warp * 6 + lane];
        acc = make_float4(a.x * s2, a.y * s2, a.z * s2, a.w * s2);
    }

    int e   = rowptr[warp];
    int end = e + deg[warp];
    for (; e + 2 <= end; e += 2) {
        int   s0 = __ldg(&csr_src[e]),  s1 = __ldg(&csr_src[e+1]);
        float w0 = __ldg(&csr_w[e]),    w1 = __ldg(&csr_w[e+1]);
        if (act) {
            float4 v0 = x4[s0 * 6 + lane];
            float4 v1 = x4[s1 * 6 + lane];
            acc.x += w0*v0.x + w1*v1.x;
            acc.y += w0*v0.y + w1*v1.y;
            acc.z += w0*v0.z + w1*v1.z;
            acc.w += w0*v0.w + w1*v1.w;
        }
    }
    for (; e < end; e++) {
        int   si = __ldg(&csr_src[e]);
        float w  = __ldg(&csr_w[e]);
        if (act) {
            float4 v = x4[si * 6 + lane];
            acc.x += w*v.x; acc.y += w*v.y; acc.z += w*v.z; acc.w += w*v.w;
        }
    }
    if (act) out4[warp * 6 + lane] = acc;
}

// ---------------- TF32 tensor-core GEMM ----------------
// out[M,128] = act(A[M,K] @ W[K,128] + b).  Block: 256 thr = 8 warps,
// tile M=64 x N=128; warp tile 16x64 (warps 4 in M x 2 in N).
// mma.sync.m16n8k8.tf32, fp32 accumulate. Inputs converted to tf32 at smem fill.

__device__ __forceinline__ unsigned f2tf32(float f) {
    unsigned u;
    asm("cvt.rna.tf32.f32 %0, %1;" : "=r"(u) : "f"(f));
    return u;
}

__device__ __forceinline__ void mma_tf32(float c[4],
                                         unsigned a0, unsigned a1, unsigned a2, unsigned a3,
                                         unsigned b0, unsigned b1) {
    asm volatile("mma.sync.aligned.m16n8k8.row.col.f32.tf32.tf32.f32 "
                 "{%0,%1,%2,%3}, {%4,%5,%6,%7}, {%8,%9}, {%0,%1,%2,%3};"
                 : "+f"(c[0]), "+f"(c[1]), "+f"(c[2]), "+f"(c[3])
                 : "r"(a0), "r"(a1), "r"(a2), "r"(a3), "r"(b0), "r"(b1));
}

#define APITCH 36
#define WPITCH 136

__global__ void __launch_bounds__(256)
k_gemm_tc(const float* __restrict__ A, int lda, int K,
          const float* __restrict__ W, const float* __restrict__ bias,
          float* __restrict__ out, int M, int do_relu) {
    __shared__ unsigned As[64 * APITCH];   // [row][k], tf32 bits
    __shared__ unsigned Ws[32 * WPITCH];   // [k][n],  tf32 bits

    int tid  = threadIdx.x;
    int lane = tid & 31;
    int wrp  = tid >> 5;
    int wm   = wrp & 3;        // M group (16 rows each)
    int wn   = wrp >> 2;       // N group (64 cols each)
    int row0 = blockIdx.x * 64;

    float acc[8][4];           // 8 n-tiles of 16x8 per warp
    #pragma unroll
    for (int t = 0; t < 8; t++)
        #pragma unroll
        for (int i = 0; i < 4; i++) acc[t][i] = 0.0f;

    int nChunks = (K + 31) / 32;
    for (int kc = 0; kc < nChunks; kc++) {
        int k0c = kc * 32;

        // --- fill A chunk: 64 rows x 32 k (tf32) ---
        #pragma unroll
        for (int q = 0; q < 2; q++) {
            int s = tid * 2 + q;           // 0..511 float4 slots
            int r = s >> 3;                // 0..63
            int kk4 = (s & 7) * 4;         // 0,4,...,28
            int grow = row0 + r;
            int k = k0c + kk4;
            float4 v = make_float4(0.f, 0.f, 0.f, 0.f);
            if (grow < M) {
                if (k + 4 <= lda) {
                    v = *(const float4*)&A[grow * lda + k];
                } else {
                    float* pv = &v.x;
                    #pragma unroll
                    for (int u = 0; u < 4; u++)
                        if (k + u < lda) pv[u] = A[grow * lda + k + u];
                }
            }
            unsigned* dst = &As[r * APITCH + kk4];
            dst[0] = f2tf32(v.x); dst[1] = f2tf32(v.y);
            dst[2] = f2tf32(v.z); dst[3] = f2tf32(v.w);
        }
        // --- fill W chunk: 32 k x 128 n (tf32) ---
        #pragma unroll
        for (int q = 0; q < 4; q++) {
            int s = tid + q * 256;         // 0..1023 float4 slots
            int kk = s >> 5;
            int c = (s & 31) * 4;
            int k = k0c + kk;
            float4 v = make_float4(0.f, 0.f, 0.f, 0.f);
            if (k < K) v = *(const float4*)&W[k * HID + c];
            unsigned* dst = &Ws[kk * WPITCH + c];
            dst[0] = f2tf32(v.x); dst[1] = f2tf32(v.y);
            dst[2] = f2tf32(v.z); dst[3] = f2tf32(v.w);
        }
        __syncthreads();

        #pragma unroll
        for (int kk = 0; kk < 4; kk++) {
            int k0 = kk * 8;
            // A fragment (m16k8): rows wm*16 + lane/4 (+8), cols k0 + lane%4 (+4)
            int ar = wm * 16 + (lane >> 2);
            int ac = k0 + (lane & 3);
            unsigned a0 = As[ar * APITCH + ac];
            unsigned a1 = As[(ar + 8) * APITCH + ac];
            unsigned a2 = As[ar * APITCH + ac + 4];
            unsigned a3 = As[(ar + 8) * APITCH + ac + 4];
            #pragma unroll
            for (int t = 0; t < 8; t++) {
                // B fragment (k8n8 col-major): k = k0 + lane%4 (+4), n = n0 + lane/4
                int bn = wn * 64 + t * 8 + (lane >> 2);
                int bk = k0 + (lane & 3);
                unsigned b0 = Ws[bk * WPITCH + bn];
                unsigned b1 = Ws[(bk + 4) * WPITCH + bn];
                mma_tf32(acc[t], a0, a1, a2, a3, b0, b1);
            }
        }
        __syncthreads();
    }

    // --- epilogue: bias + relu, float2 stores ---
    int r_lo = row0 + wm * 16 + (lane >> 2);
    int r_hi = r_lo + 8;
    #pragma unroll
    for (int t = 0; t < 8; t++) {
        int col = wn * 64 + t * 8 + 2 * (lane & 3);
        float bx = bias[col], by = bias[col + 1];
        float v0 = acc[t][0] + bx, v1 = acc[t][1] + by;
        float v2 = acc[t][2] + bx, v3 = acc[t][3] + by;
        if (do_relu) {
            v0 = fmaxf(v0, 0.f); v1 = fmaxf(v1, 0.f);
            v2 = fmaxf(v2, 0.f); v3 = fmaxf(v3, 0.f);
        }
        if (r_lo < M) *(float2*)&out[r_lo * HID + col] = make_float2(v0, v1);
        if (r_hi < M) *(float2*)&out[r_hi * HID + col] = make_float2(v2, v3);
    }
}

// ---------------- launch ----------------
extern "C" void kernel_launch(void* const* d_in, const int* in_sizes, int n_in,
                              void* d_out, int out_size) {
    const float* x  = (const float*)d_in[0];
    const int*   ei = (const int*)d_in[1];   // int32 (JAX x64 disabled)
    const float* W1 = (const float*)d_in[2]; const float* b1 = (const float*)d_in[3];
    const float* W2 = (const float*)d_in[4]; const float* b2 = (const float*)d_in[5];
    const float* W3 = (const float*)d_in[6]; const float* b3 = (const float*)d_in[7];
    const float* W4 = (const float*)d_in[8]; const float* b4 = (const float*)d_in[9];
    float* out = (float*)d_out;

    int E = in_sizes[1] / 2;
    int N = out_size / HID;

    void* p;
    cudaGetSymbolAddress(&p, g_dis);     float* dis  = (float*)p;
    cudaGetSymbolAddress(&p, g_xpad);    float* xpad = (float*)p;
    cudaGetSymbolAddress(&p, g_aggx);    float* aggx = (float*)p;
    cudaGetSymbolAddress(&p, g_bufA);    float* bufA = (float*)p;
    cudaGetSymbolAddress(&p, g_bufB);    float* bufB = (float*)p;
    cudaGetSymbolAddress(&p, g_deg);     int* deg    = (int*)p;
    cudaGetSymbolAddress(&p, g_rowptr);  int* rowptr = (int*)p;
    cudaGetSymbolAddress(&p, g_cursor);  int* cursor = (int*)p;
    cudaGetSymbolAddress(&p, g_bsum);    int* bsum   = (int*)p;
    cudaGetSymbolAddress(&p, g_csr_src); int* csr_src= (int*)p;
    cudaGetSymbolAddress(&p, g_csr_w);   float* csr_w= (float*)p;

    const int T = 256;
    int blkN    = (N + T - 1) / T;
    int blkE    = (E + T - 1) / T;
    int blkPrep = (N * INP + T - 1) / T;
    int nScanB  = (N + SCAN_B - 1) / SCAN_B;
    int blkWarp = (N * 32 + T - 1) / T;
    int blkG    = (N + 63) / 64;

    // norm + CSR build
    k_deg_zero<<<blkN, T>>>(deg, N);
    k_deg_count<<<blkE, T>>>(ei, deg, E);
    k_dis<<<blkN, T>>>(deg, dis, N);
    k_scan_block<<<nScanB, SCAN_B>>>(deg, rowptr, bsum, N);
    k_scan_bsum<<<1, 32>>>(bsum, nScanB);
    k_scan_add<<<blkN, T>>>(rowptr, cursor, bsum, N);
    k_fill<<<blkE, T>>>(ei, dis, cursor, csr_src, csr_w, E);

    // layer 1: pad x, gather 24-wide, GEMM 23->128 + relu
    k_prep_x<<<blkPrep, T>>>(x, xpad, N);
    k_gather24<<<blkWarp, T>>>(rowptr, deg, csr_src, csr_w, dis,
                               (const float4*)xpad, (float4*)aggx, N);
    k_gemm_tc<<<blkG, T>>>(aggx, INP, IN_DIM, W1, b1, bufA, N, 1);

    // layer 2
    k_gather128<<<blkWarp, T>>>(rowptr, deg, csr_src, csr_w, dis,
                                (const float4*)bufA, (float4*)bufB, N);
    k_gemm_tc<<<blkG, T>>>(bufB, HID, HID, W2, b2, bufB, N, 1);

    // layer 3
    k_gather128<<<blkWarp, T>>>(rowptr, deg, csr_src, csr_w, dis,
                                (const float4*)bufB, (float4*)bufA, N);
    k_gemm_tc<<<blkG, T>>>(bufA, HID, HID, W3, b3, bufA, N, 1);

    // layer 4 (no relu) -> out
    k_gather128<<<blkWarp, T>>>(rowptr, deg, csr_src, csr_w, dis,
                                (const float4*)bufA, (float4*)bufB, N);
    k_gemm_tc<<<blkG, T>>>(bufB, HID, HID, W4, b4, out, N, 0);
}